// round 6
// baseline (speedup 1.0000x reference)
#include <cuda_runtime.h>

#define BB   32
#define NN   1024
#define WW_  128
#define RR   4
#define SEQ  512
#define DIN  512
#define IFACE 919

// Flattened output offsets (tuple concat order: out, memory, link, usage, prec, ww, rw)
#define OUT_OFF    0ull
#define MEM_OFF    16384ull
#define LINK_OFF   4210688ull
#define USAGE_OFF  37765120ull
#define PREC_OFF   37797888ull
#define WWO_OFF    37830656ull
#define RW_OFF     37863424ull
#define LINK_BYTES (33554432ull * 4ull)   // 134 MB of zeros

// Scratch (no allocations allowed)
__device__ float g_part[16 * BB * DIN];
__device__ float g_er[BB * WW_];
__device__ float g_wv[BB * WW_];

__device__ __forceinline__ float sigmoidf(float x) {
    return 1.0f / (1.0f + expf(-x));
}

// ---------------------------------------------------------------------------
// k_mean: partial mean of x over seq. grid 256, block 256 (proven layout).
// block (b,c): c-th 64-row chunk of batch b, two 32-row halves across threads.
// ---------------------------------------------------------------------------
__global__ void __launch_bounds__(256)
k_mean(const float* __restrict__ x) {
    int bid = blockIdx.x, t = threadIdx.x;
    int b = bid >> 3, c = bid & 7;
    int col = t & 127;
    int h   = t >> 7;
    const float4* xp = (const float4*)(x + (size_t)b * SEQ * DIN);
    float4 acc = make_float4(0.f, 0.f, 0.f, 0.f);
    int s0 = c * 64 + h * 32;
#pragma unroll 4
    for (int s = s0; s < s0 + 32; s++) {
        float4 v = xp[s * 128 + col];
        acc.x += v.x; acc.y += v.y; acc.z += v.z; acc.w += v.w;
    }
    ((float4*)g_part)[((c * 2 + h) * BB + b) * 128 + col] = acc;
}

// ---------------------------------------------------------------------------
// k23: one block per batch. Combine partials -> mean (smem), compute ONLY the
// needed iface columns [645,919), activations, then write all small output
// sections: out, ww, prec, usage, rw (~1MB total).
// ---------------------------------------------------------------------------
__global__ void __launch_bounds__(256)
k23_batch(const float* __restrict__ Wm, float* __restrict__ out) {
    int b = blockIdx.x, t = threadIdx.x;
    __shared__ float mx[DIN];
    __shared__ float s_rm1[RR], s_fg[RR], s_q[RR];
    __shared__ float s_pw[16];
    __shared__ float s_c1, s_c2, s_u;

    // combine 16 partial chunks -> mean vector in smem
    for (int i = t; i < DIN; i += 256) {
        float s = 0.f;
#pragma unroll
        for (int c = 0; c < 16; c++) s += g_part[(c * BB + b) * DIN + i];
        mx[i] = s * (1.0f / 512.0f);
    }
    __syncthreads();

    // iface[j] = mean . W[:,j] for j in [645, 919) only
    float f_loc[2];
    int   j_loc[2];
    int nj = 0;
    for (int j = 645 + t; j < IFACE; j += 256) {
        float acc = 0.f;
#pragma unroll 8
        for (int k = 0; k < DIN; k++) acc = fmaf(mx[k], Wm[k * IFACE + j], acc);
        f_loc[nj] = acc; j_loc[nj] = j; nj++;
    }
    __syncthreads();
    // scatter: mx[0..127]=erase raw, [128..255]=write_vec, [256..259]=free gates,
    // [260]=alloc gate, [261]=write gate, [262..273]=read modes
    for (int i = 0; i < nj; i++) mx[j_loc[i] - 645] = f_loc[i];
    __syncthreads();

    if (t < 128) {
        g_er[b * WW_ + t] = sigmoidf(mx[t]);
        g_wv[b * WW_ + t] = mx[128 + t];
    }
    if (t < RR) {
        float m0 = mx[262 + t], m1 = mx[266 + t], m2 = mx[270 + t];
        float mmax = fmaxf(m0, fmaxf(m1, m2));
        float e0 = expf(m0 - mmax), e1 = expf(m1 - mmax), e2 = expf(m2 - mmax);
        float rm1 = e1 / (e0 + e1 + e2);
        s_rm1[t] = rm1;
        float q = rm1 * (1.0f / 1024.0f);   // exact /2^10
        s_q[t] = q;
        s_fg[t] = sigmoidf(mx[256 + t]);
    }
    __syncthreads();
    if (t == 0) {
        float ret = 1.0f;
#pragma unroll
        for (int r = 0; r < RR; r++) ret *= (1.0f - s_fg[r] * s_q[r]);
        float u = 1e-6f * ret;              // usage (constant over n)
        s_u = u;
        float ag = sigmoidf(mx[260]);
        float wg = sigmoidf(mx[261]);
        s_c1 = wg * ag * (1.0f - u);
        s_c2 = wg * (1.0f - ag) * (1.0f / 1024.0f);
        float sh = 1.0f;                    // exact sequential cumprod prefix
#pragma unroll
        for (int i = 0; i < 16; i++) { s_pw[i] = sh; sh *= u; }
    }
    __syncthreads();

    // out[b, w*4+r] = 1e-6 * rm1[r]
    if (t < 128) {
        float4 ov = make_float4(1e-6f * s_rm1[0], 1e-6f * s_rm1[1],
                                1e-6f * s_rm1[2], 1e-6f * s_rm1[3]);
        ((float4*)(out + OUT_OFF))[b * 128 + t] = ov;
    }
    // ww / prec / usage / rw sections
    float c1 = s_c1, c2 = s_c2, u = s_u;
    float4 q4 = make_float4(s_q[0], s_q[1], s_q[2], s_q[3]);
#pragma unroll
    for (int n = t; n < NN; n += 256) {
        float shifted = (n < 16) ? s_pw[n] : 0.0f;
        float ww = fmaf(c1, shifted, c2);
        out[WWO_OFF + (size_t)b * NN + n]   = ww;
        out[PREC_OFF + (size_t)b * NN + n]  = ww;   // prec == ww
        out[USAGE_OFF + (size_t)b * NN + n] = u;
        ((float4*)(out + RW_OFF))[b * NN + n] = q4;
    }
}

// ---------------------------------------------------------------------------
// k4: memory fill only. grid 4096, block 256, 1 float4/thread (proven pattern).
// ---------------------------------------------------------------------------
__global__ void __launch_bounds__(256)
k4_mem(float* __restrict__ out) {
    int v = blockIdx.x * 256 + threadIdx.x;  // float4 index into memory
    int b = v >> 15;                          // 32768 f4 per batch
    int rem = v & 32767;
    int n  = rem >> 5;
    int w4 = rem & 31;
    float ww = __ldg(out + WWO_OFF + (size_t)b * NN + n);
    float4 e  = ((const float4*)g_er)[b * 32 + w4];
    float4 wv = ((const float4*)g_wv)[b * 32 + w4];
    float4 m;
    m.x = 1e-6f * (1.0f - ww * e.x) + ww * wv.x;
    m.y = 1e-6f * (1.0f - ww * e.y) + ww * wv.y;
    m.z = 1e-6f * (1.0f - ww * e.z) + ww * wv.z;
    m.w = 1e-6f * (1.0f - ww * e.w) + ww * wv.w;
    ((float4*)(out + MEM_OFF))[v] = m;
}

extern "C" void kernel_launch(void* const* d_in, const int* in_sizes, int n_in,
                              void* d_out, int out_size) {
    const float* x  = (const float*)d_in[0];
    const float* Wm = (const float*)d_in[1];
    float* out = (float*)d_out;

    // link output is identically zero; driver fill path is fastest in steady state
    cudaMemsetAsync(out + LINK_OFF, 0, LINK_BYTES);

    k_mean<<<256, 256>>>(x);
    k23_batch<<<BB, 256>>>(Wm, out);
    k4_mem<<<4096, 256>>>(out);
}

// round 7
// speedup vs baseline: 1.6315x; 1.6315x over previous
#include <cuda_runtime.h>

#define BB   32
#define NN   1024
#define WW_  128
#define RR   4
#define SEQ  512
#define DIN  512
#define IFACE 919

// Flattened output offsets (tuple concat order: out, memory, link, usage, prec, ww, rw)
#define OUT_OFF    0ull
#define MEM_OFF    16384ull
#define LINK_OFF   4210688ull
#define USAGE_OFF  37765120ull
#define PREC_OFF   37797888ull
#define WWO_OFF    37830656ull
#define RW_OFF     37863424ull
#define LINK_F4    8388608ull      // 33,554,432 floats / 4

#define MEAN_BLKS  512
#define ZERO_BLKS  1536
#define N1_BLKS    (MEAN_BLKS + ZERO_BLKS)

// Scratch (no allocations allowed)
__device__ float g_part[32 * BB * DIN];
__device__ float g_er[BB * WW_];
__device__ float g_wv[BB * WW_];

__device__ __forceinline__ float sigmoidf(float x) {
    return 1.0f / (1.0f + expf(-x));
}

// ---------------------------------------------------------------------------
// Node 1: fused link-zero (134MB, __stcs evict-first streaming stores)
//         + mean partials of x (33.5MB, __ldcs streaming reads).
// grid 2048 x 256.
// ---------------------------------------------------------------------------
__global__ void __launch_bounds__(256)
k1_zero_mean(const float* __restrict__ x, float* __restrict__ out) {
    int bid = blockIdx.x, t = threadIdx.x;
    if (bid < MEAN_BLKS) {
        // block (b, c): 32-row chunk c of batch b; threads split into 2 halves
        int b = bid >> 4, c = bid & 15;
        int col = t & 127;          // float4 column (512 floats / 4)
        int h   = t >> 7;           // 16-row half
        int cc  = c * 2 + h;        // chunk-half id in [0, 32)
        const float4* xp = (const float4*)(x + (size_t)b * SEQ * DIN);
        float4 acc = make_float4(0.f, 0.f, 0.f, 0.f);
        int s0 = c * 32 + h * 16;
#pragma unroll
        for (int s = s0; s < s0 + 16; s += 2) {   // 2-way ILP on the loads
            float4 v0 = __ldcs(&xp[s * 128 + col]);
            float4 v1 = __ldcs(&xp[(s + 1) * 128 + col]);
            acc.x += v0.x + v1.x; acc.y += v0.y + v1.y;
            acc.z += v0.z + v1.z; acc.w += v0.w + v1.w;
        }
        ((float4*)g_part)[(cc * BB + b) * 128 + col] = acc;
    } else {
        float4 z = make_float4(0.f, 0.f, 0.f, 0.f);
        float4* p = (float4*)(out + LINK_OFF);
        size_t stride = (size_t)ZERO_BLKS * 256;
        // LINK_F4 / (ZERO_BLKS*256) = 21.33 -> 22 grid-stride steps max
        for (size_t i = (size_t)(bid - MEAN_BLKS) * 256 + t; i < LINK_F4; i += stride)
            __stcs(&p[i], z);       // evict-first: don't thrash L2 with dead lines
    }
}

// ---------------------------------------------------------------------------
// Node 2: one block per batch. Combine 32 partial chunks -> mean (smem),
// compute ONLY the needed iface columns [645,919), activations, then write
// all small output sections: out, ww, prec, usage, rw (~1MB total).
// ---------------------------------------------------------------------------
__global__ void __launch_bounds__(256)
k2_batch(const float* __restrict__ Wm, float* __restrict__ out) {
    int b = blockIdx.x, t = threadIdx.x;
    __shared__ float mx[DIN];
    __shared__ float s_rm1[RR], s_fg[RR], s_q[RR];
    __shared__ float s_pw[16];
    __shared__ float s_c1, s_c2, s_u;

    for (int i = t; i < DIN; i += 256) {
        float s = 0.f;
#pragma unroll
        for (int c = 0; c < 32; c++) s += g_part[(c * BB + b) * DIN + i];
        mx[i] = s * (1.0f / 512.0f);
    }
    __syncthreads();

    // iface[j] = mean . W[:,j] for j in [645, 919) only
    float f_loc[2];
    int   j_loc[2];
    int nj = 0;
    for (int j = 645 + t; j < IFACE; j += 256) {
        float acc = 0.f;
#pragma unroll 8
        for (int k = 0; k < DIN; k++) acc = fmaf(mx[k], Wm[k * IFACE + j], acc);
        f_loc[nj] = acc; j_loc[nj] = j; nj++;
    }
    __syncthreads();
    // scatter: mx[0..127]=erase raw, [128..255]=write_vec, [256..259]=free gates,
    // [260]=alloc gate, [261]=write gate, [262..273]=read modes
    for (int i = 0; i < nj; i++) mx[j_loc[i] - 645] = f_loc[i];
    __syncthreads();

    if (t < 128) {
        g_er[b * WW_ + t] = sigmoidf(mx[t]);
        g_wv[b * WW_ + t] = mx[128 + t];
    }
    if (t < RR) {
        float m0 = mx[262 + t], m1 = mx[266 + t], m2 = mx[270 + t];
        float mmax = fmaxf(m0, fmaxf(m1, m2));
        float e0 = expf(m0 - mmax), e1 = expf(m1 - mmax), e2 = expf(m2 - mmax);
        float rm1 = e1 / (e0 + e1 + e2);
        s_rm1[t] = rm1;
        float q = rm1 * (1.0f / 1024.0f);   // exact /2^10
        s_q[t] = q;
        s_fg[t] = sigmoidf(mx[256 + t]);
    }
    __syncthreads();
    if (t == 0) {
        float ret = 1.0f;
#pragma unroll
        for (int r = 0; r < RR; r++) ret *= (1.0f - s_fg[r] * s_q[r]);
        float u = 1e-6f * ret;              // usage (constant over n)
        s_u = u;
        float ag = sigmoidf(mx[260]);
        float wg = sigmoidf(mx[261]);
        s_c1 = wg * ag * (1.0f - u);
        s_c2 = wg * (1.0f - ag) * (1.0f / 1024.0f);
        float sh = 1.0f;                    // exact sequential cumprod prefix
#pragma unroll
        for (int i = 0; i < 16; i++) { s_pw[i] = sh; sh *= u; }
    }
    __syncthreads();

    // out[b, w*4+r] = 1e-6 * rm1[r]
    if (t < 128) {
        float4 ov = make_float4(1e-6f * s_rm1[0], 1e-6f * s_rm1[1],
                                1e-6f * s_rm1[2], 1e-6f * s_rm1[3]);
        ((float4*)(out + OUT_OFF))[b * 128 + t] = ov;
    }
    // ww / prec / usage / rw sections (ww is re-read by node 3 -> normal stores)
    float c1 = s_c1, c2 = s_c2, u = s_u;
    float4 q4 = make_float4(s_q[0], s_q[1], s_q[2], s_q[3]);
#pragma unroll
    for (int n = t; n < NN; n += 256) {
        float shifted = (n < 16) ? s_pw[n] : 0.0f;
        float ww = fmaf(c1, shifted, c2);
        out[WWO_OFF + (size_t)b * NN + n]   = ww;
        out[PREC_OFF + (size_t)b * NN + n]  = ww;   // prec == ww
        out[USAGE_OFF + (size_t)b * NN + n] = u;
        ((float4*)(out + RW_OFF))[b * NN + n] = q4;
    }
}

// ---------------------------------------------------------------------------
// Node 3: memory fill (17MB). grid 2048, block 256, 2 float4/thread,
// evict-first stores.
// ---------------------------------------------------------------------------
__global__ void __launch_bounds__(256)
k3_mem(float* __restrict__ out) {
    int base = blockIdx.x * 512 + threadIdx.x;
#pragma unroll
    for (int i = 0; i < 2; i++) {
        int v = base + i * 256;              // float4 index into memory
        int b = v >> 15;                     // 32768 f4 per batch
        int rem = v & 32767;
        int n  = rem >> 5;
        int w4 = rem & 31;
        float ww = __ldg(out + WWO_OFF + (size_t)b * NN + n);
        float4 e  = ((const float4*)g_er)[b * 32 + w4];
        float4 wv = ((const float4*)g_wv)[b * 32 + w4];
        float4 m;
        m.x = 1e-6f * (1.0f - ww * e.x) + ww * wv.x;
        m.y = 1e-6f * (1.0f - ww * e.y) + ww * wv.y;
        m.z = 1e-6f * (1.0f - ww * e.z) + ww * wv.z;
        m.w = 1e-6f * (1.0f - ww * e.w) + ww * wv.w;
        __stcs(&((float4*)(out + MEM_OFF))[v], m);
    }
}

extern "C" void kernel_launch(void* const* d_in, const int* in_sizes, int n_in,
                              void* d_out, int out_size) {
    const float* x  = (const float*)d_in[0];
    const float* Wm = (const float*)d_in[1];
    float* out = (float*)d_out;

    k1_zero_mean<<<N1_BLKS, 256>>>(x, out);
    k2_batch<<<BB, 256>>>(Wm, out);
    k3_mem<<<2048, 256>>>(out);
}

// round 8
// speedup vs baseline: 1.6455x; 1.0086x over previous
#include <cuda_runtime.h>

#define BB   32
#define NN   1024
#define WW_  128
#define RR   4
#define SEQ  512
#define DIN  512
#define IFACE 919

// Flattened output offsets (tuple concat order: out, memory, link, usage, prec, ww, rw)
#define OUT_OFF    0ull
#define MEM_OFF    16384ull
#define LINK_OFF   4210688ull
#define USAGE_OFF  37765120ull
#define PREC_OFF   37797888ull
#define WWO_OFF    37830656ull
#define RW_OFF     37863424ull
#define LINK_F4    8388608ull      // 33,554,432 floats / 4

#define MEAN_BLKS  512
#define ZERO_BLKS  2048            // 2048*256*16 == LINK_F4 exactly
#define N1_BLKS    (MEAN_BLKS + ZERO_BLKS)

// Scratch (no allocations allowed)
__device__ float g_part[32 * BB * DIN];
__device__ float g_er[BB * WW_];
__device__ float g_wv[BB * WW_];

__device__ __forceinline__ float sigmoidf(float x) {
    return 1.0f / (1.0f + expf(-x));
}

// ---------------------------------------------------------------------------
// Node 1: fused link-zero (134MB, __stcs evict-first, exactly 16 stores/thread)
//         + mean partials of x (33.5MB, __ldcs streaming reads).
// grid 2560 x 256.
// ---------------------------------------------------------------------------
__global__ void __launch_bounds__(256)
k1_zero_mean(const float* __restrict__ x, float* __restrict__ out) {
    int bid = blockIdx.x, t = threadIdx.x;
    if (bid < MEAN_BLKS) {
        // block (b, c): 32-row chunk c of batch b; threads split into 2 halves
        int b = bid >> 4, c = bid & 15;
        int col = t & 127;          // float4 column (512 floats / 4)
        int h   = t >> 7;           // 16-row half
        int cc  = c * 2 + h;        // chunk-half id in [0, 32)
        const float4* xp = (const float4*)(x + (size_t)b * SEQ * DIN);
        float4 acc = make_float4(0.f, 0.f, 0.f, 0.f);
        int s0 = c * 32 + h * 16;
#pragma unroll
        for (int s = s0; s < s0 + 16; s += 2) {   // 2-way ILP on the loads
            float4 v0 = __ldcs(&xp[s * 128 + col]);
            float4 v1 = __ldcs(&xp[(s + 1) * 128 + col]);
            acc.x += v0.x + v1.x; acc.y += v0.y + v1.y;
            acc.z += v0.z + v1.z; acc.w += v0.w + v1.w;
        }
        ((float4*)g_part)[(cc * BB + b) * 128 + col] = acc;
    } else {
        float4 z = make_float4(0.f, 0.f, 0.f, 0.f);
        float4* p = (float4*)(out + LINK_OFF);
        size_t base = (size_t)(bid - MEAN_BLKS) * 256 + t;
        size_t stride = (size_t)ZERO_BLKS * 256;
#pragma unroll
        for (int i = 0; i < 16; i++)            // exact cover, no bounds check
            __stcs(&p[base + (size_t)i * stride], z);
    }
}

// ---------------------------------------------------------------------------
// Node 2: one block per batch. Combine 32 partial chunks -> mean (smem),
// compute ONLY the needed iface columns [645,919), activations, then write
// all small output sections: out, ww, prec, usage, rw (~1MB total).
// ---------------------------------------------------------------------------
__global__ void __launch_bounds__(256)
k2_batch(const float* __restrict__ Wm, float* __restrict__ out) {
    int b = blockIdx.x, t = threadIdx.x;
    __shared__ float mx[DIN];
    __shared__ float s_rm1[RR], s_fg[RR], s_q[RR];
    __shared__ float s_pw[16];
    __shared__ float s_c1, s_c2, s_u;

    for (int i = t; i < DIN; i += 256) {
        float s = 0.f;
#pragma unroll
        for (int c = 0; c < 32; c++) s += g_part[(c * BB + b) * DIN + i];
        mx[i] = s * (1.0f / 512.0f);
    }
    __syncthreads();

    // iface[j] = mean . W[:,j] for j in [645, 919) only
    float f_loc[2];
    int   j_loc[2];
    int nj = 0;
    for (int j = 645 + t; j < IFACE; j += 256) {
        float acc = 0.f;
#pragma unroll 8
        for (int k = 0; k < DIN; k++) acc = fmaf(mx[k], Wm[k * IFACE + j], acc);
        f_loc[nj] = acc; j_loc[nj] = j; nj++;
    }
    __syncthreads();
    // scatter: mx[0..127]=erase raw, [128..255]=write_vec, [256..259]=free gates,
    // [260]=alloc gate, [261]=write gate, [262..273]=read modes
    for (int i = 0; i < nj; i++) mx[j_loc[i] - 645] = f_loc[i];
    __syncthreads();

    if (t < 128) {
        g_er[b * WW_ + t] = sigmoidf(mx[t]);
        g_wv[b * WW_ + t] = mx[128 + t];
    }
    if (t < RR) {
        float m0 = mx[262 + t], m1 = mx[266 + t], m2 = mx[270 + t];
        float mmax = fmaxf(m0, fmaxf(m1, m2));
        float e0 = expf(m0 - mmax), e1 = expf(m1 - mmax), e2 = expf(m2 - mmax);
        float rm1 = e1 / (e0 + e1 + e2);
        s_rm1[t] = rm1;
        float q = rm1 * (1.0f / 1024.0f);   // exact /2^10
        s_q[t] = q;
        s_fg[t] = sigmoidf(mx[256 + t]);
    }
    __syncthreads();
    if (t == 0) {
        float ret = 1.0f;
#pragma unroll
        for (int r = 0; r < RR; r++) ret *= (1.0f - s_fg[r] * s_q[r]);
        float u = 1e-6f * ret;              // usage (constant over n)
        s_u = u;
        float ag = sigmoidf(mx[260]);
        float wg = sigmoidf(mx[261]);
        s_c1 = wg * ag * (1.0f - u);
        s_c2 = wg * (1.0f - ag) * (1.0f / 1024.0f);
        float sh = 1.0f;                    // exact sequential cumprod prefix
#pragma unroll
        for (int i = 0; i < 16; i++) { s_pw[i] = sh; sh *= u; }
    }
    __syncthreads();

    // out[b, w*4+r] = 1e-6 * rm1[r]   (write-only -> evict-first)
    if (t < 128) {
        float4 ov = make_float4(1e-6f * s_rm1[0], 1e-6f * s_rm1[1],
                                1e-6f * s_rm1[2], 1e-6f * s_rm1[3]);
        __stcs(&((float4*)(out + OUT_OFF))[b * 128 + t], ov);
    }
    // ww (re-read by node 3 -> cached store) / prec / usage / rw (write-only)
    float c1 = s_c1, c2 = s_c2, u = s_u;
    float4 q4 = make_float4(s_q[0], s_q[1], s_q[2], s_q[3]);
#pragma unroll
    for (int n = t; n < NN; n += 256) {
        float shifted = (n < 16) ? s_pw[n] : 0.0f;
        float ww = fmaf(c1, shifted, c2);
        out[WWO_OFF + (size_t)b * NN + n] = ww;              // cached: k3 re-reads
        __stcs(out + PREC_OFF + (size_t)b * NN + n, ww);
        __stcs(out + USAGE_OFF + (size_t)b * NN + n, u);
        __stcs(&((float4*)(out + RW_OFF))[b * NN + n], q4);
    }
}

// ---------------------------------------------------------------------------
// Node 3: memory fill (17MB). grid 4096, block 256, 1 float4/thread,
// evict-first stores.
// ---------------------------------------------------------------------------
__global__ void __launch_bounds__(256)
k3_mem(float* __restrict__ out) {
    int v = blockIdx.x * 256 + threadIdx.x;  // float4 index into memory
    int b = v >> 15;                          // 32768 f4 per batch
    int rem = v & 32767;
    int n  = rem >> 5;
    int w4 = rem & 31;
    float ww = __ldg(out + WWO_OFF + (size_t)b * NN + n);
    float4 e  = ((const float4*)g_er)[b * 32 + w4];
    float4 wv = ((const float4*)g_wv)[b * 32 + w4];
    float4 m;
    m.x = 1e-6f * (1.0f - ww * e.x) + ww * wv.x;
    m.y = 1e-6f * (1.0f - ww * e.y) + ww * wv.y;
    m.z = 1e-6f * (1.0f - ww * e.z) + ww * wv.z;
    m.w = 1e-6f * (1.0f - ww * e.w) + ww * wv.w;
    __stcs(&((float4*)(out + MEM_OFF))[v], m);
}

extern "C" void kernel_launch(void* const* d_in, const int* in_sizes, int n_in,
                              void* d_out, int out_size) {
    const float* x  = (const float*)d_in[0];
    const float* Wm = (const float*)d_in[1];
    float* out = (float*)d_out;

    k1_zero_mean<<<N1_BLKS, 256>>>(x, out);
    k2_batch<<<BB, 256>>>(Wm, out);
    k3_mem<<<4096, 256>>>(out);
}